// round 1
// baseline (speedup 1.0000x reference)
#include <cuda_runtime.h>
#include <cstdint>
#include <cstddef>

#define BSZ 32
#define SEQ 256
#define EMBD 256
#define HIDD 512
#define NTAG 45
#define NTOK (BSZ*SEQ)     // 8192
#define G4H  2048          // 4*HID
#define GN   4096          // both directions

// ---------------- scratch (static device allocations; no cudaMalloc) ----------------
__device__ __align__(16) float g_G[(size_t)NTOK * GN];           // input proj + bias, [token][4096]
__device__ __align__(16) float g_hseq[2 * SEQ * BSZ * HIDD];     // [dir][t][b][h]
__device__ __align__(16) float g_hbuf[2 * 2 * BSZ * HIDD];       // [phase][dir][b][h]
__device__ __align__(16) float g_em[(size_t)NTOK * NTAG];        // emissions [token][tag]
__device__ float g_loss[BSZ];
__device__ unsigned g_cnt[2];
__device__ volatile unsigned g_gen[2];

// =====================================================================
// Kernel 1: G[token][n] = dot(emb[x[token]], W[n]) + bias[n]
//   W = concat(w_ih_f, w_ih_b) rows, n in [0,4096). 128x128x16 tiles.
// =====================================================================
__global__ __launch_bounds__(256) void gemm_in(
    const int* __restrict__ x, const float* __restrict__ emb,
    const float* __restrict__ wf, const float* __restrict__ wb,
    const float* __restrict__ bf, const float* __restrict__ bb)
{
    __shared__ float sA[16 * 132];
    __shared__ float sW[16 * 132];
    const int tid = threadIdx.x;
    const int bx = blockIdx.x;   // n tile (0..31)
    const int by = blockIdx.y;   // m tile (0..63)
    const int tx = tid & 15, ty = tid >> 4;

    float acc[8][8];
#pragma unroll
    for (int i = 0; i < 8; ++i)
#pragma unroll
        for (int j = 0; j < 8; ++j) acc[i][j] = 0.f;

    // each thread loads 2 float4 of A-tile and 2 float4 of W-tile per K-iter
    const int f4a = tid * 2, f4b = tid * 2 + 1;
    const int ra = f4a >> 2, qa = (f4a & 3) * 4;
    const int rb = f4b >> 2, qb = (f4b & 3) * 4;
    const float* arow_a = emb + (size_t)x[by * 128 + ra] * EMBD;
    const float* arow_b = emb + (size_t)x[by * 128 + rb] * EMBD;
    const int na = bx * 128 + ra, nb = bx * 128 + rb;
    const float* wrow_a = (na < G4H) ? (wf + (size_t)na * EMBD) : (wb + (size_t)(na - G4H) * EMBD);
    const float* wrow_b = (nb < G4H) ? (wf + (size_t)nb * EMBD) : (wb + (size_t)(nb - G4H) * EMBD);

    for (int kb = 0; kb < EMBD; kb += 16) {
        __syncthreads();
        float4 va = *(const float4*)(arow_a + kb + qa);
        float4 vb = *(const float4*)(arow_b + kb + qb);
        float4 wa = *(const float4*)(wrow_a + kb + qa);
        float4 wv = *(const float4*)(wrow_b + kb + qb);
        // store transposed: s[k][row]
        sA[(qa + 0) * 132 + ra] = va.x; sA[(qa + 1) * 132 + ra] = va.y;
        sA[(qa + 2) * 132 + ra] = va.z; sA[(qa + 3) * 132 + ra] = va.w;
        sA[(qb + 0) * 132 + rb] = vb.x; sA[(qb + 1) * 132 + rb] = vb.y;
        sA[(qb + 2) * 132 + rb] = vb.z; sA[(qb + 3) * 132 + rb] = vb.w;
        sW[(qa + 0) * 132 + ra] = wa.x; sW[(qa + 1) * 132 + ra] = wa.y;
        sW[(qa + 2) * 132 + ra] = wa.z; sW[(qa + 3) * 132 + ra] = wa.w;
        sW[(qb + 0) * 132 + rb] = wv.x; sW[(qb + 1) * 132 + rb] = wv.y;
        sW[(qb + 2) * 132 + rb] = wv.z; sW[(qb + 3) * 132 + rb] = wv.w;
        __syncthreads();
#pragma unroll
        for (int kk = 0; kk < 16; ++kk) {
            float4 a0 = *(const float4*)&sA[kk * 132 + ty * 8];
            float4 a1 = *(const float4*)&sA[kk * 132 + ty * 8 + 4];
            float4 b0 = *(const float4*)&sW[kk * 132 + tx * 8];
            float4 b1 = *(const float4*)&sW[kk * 132 + tx * 8 + 4];
            float av[8] = {a0.x, a0.y, a0.z, a0.w, a1.x, a1.y, a1.z, a1.w};
            float bv[8] = {b0.x, b0.y, b0.z, b0.w, b1.x, b1.y, b1.z, b1.w};
#pragma unroll
            for (int i = 0; i < 8; ++i)
#pragma unroll
                for (int j = 0; j < 8; ++j)
                    acc[i][j] += av[i] * bv[j];
        }
    }
    const int m0 = by * 128 + ty * 8;
    const int n0 = bx * 128 + tx * 8;
#pragma unroll
    for (int i = 0; i < 8; ++i) {
        float* dst = g_G + (size_t)(m0 + i) * GN + n0;
#pragma unroll
        for (int j = 0; j < 8; ++j) {
            int n = n0 + j;
            float bias = (n < G4H) ? bf[n] : bb[n - G4H];
            dst[j] = acc[i][j] + bias;
        }
    }
}

// =====================================================================
// Kernel 2: persistent bidirectional LSTM recurrence.
// grid = 128 blocks (64 per direction), 256 threads, 1 block/SM.
// Block owns 8 hidden indices (32 gate rows) x all 32 batches.
// w_hh slice resident in smem for all 256 steps; h double-buffered in
// global and staged into smem each step; 8-way K split + smem reduce;
// per-direction 64-block spin barrier per step.
// =====================================================================
__device__ __forceinline__ float sigmoidf_(float v) { return 1.f / (1.f + __expf(-v)); }

__global__ __launch_bounds__(256) void lstm_rec(
    const float* __restrict__ whf, const float* __restrict__ whb)
{
    extern __shared__ float smem[];
    float* sw  = smem;                 // 32 rows x 516 (row = g*8+jj)
    float* sh  = smem + 32 * 516;      // 32 rows x 516 (row = b)
    float* red = smem + 64 * 516;      // [8 kseg][32 unit][32]

    const int tid = threadIdx.x;
    const int dir = blockIdx.x >> 6;   // 0 fwd, 1 bwd
    const int blk = blockIdx.x & 63;
    const int jbase = blk * 8;
    const float* whh = dir ? whb : whf;

    // load owned w_hh rows: 32 rows x 512 floats
    for (int idx = tid; idx < 32 * 128; idx += 256) {
        int row = idx >> 7;
        int q = (idx & 127) * 4;
        int g = row >> 3, j = row & 7;
        *(float4*)&sw[row * 516 + q] =
            *(const float4*)(whh + (size_t)(g * 512 + jbase + j) * HIDD + q);
    }

    // dot-phase decomposition
    const int kseg = tid >> 5;         // 0..7 (64 k each)
    const int unit = tid & 31;         // (jj, boct)
    const int jj = unit >> 2;          // 0..7
    const int boct = unit & 3;         // 0..3 (8 batches)
    const int kb = kseg * 64;
    // finalize decomposition: thread owns cell (fj, fb)
    const int fj = tid >> 5;           // 0..7
    const int fb = tid & 31;           // 0..31
    const int jglob = jbase + fj;
    const int funit = fj * 4 + (fb >> 3);
    const int fbb = fb & 7;

    float c_state = 0.f;
    int p = 0;
    __syncthreads();

    for (int t = 0; t < SEQ; ++t) {
        const int t_eff = dir ? (SEQ - 1 - t) : t;
        float d0 = 0.f, d1 = 0.f, d2 = 0.f, d3 = 0.f;
        if (t > 0) {
            // stage h_prev (bypass L1: written by other SMs last step)
            const float* hsrc = g_hbuf + (size_t)((p * 2 + dir) * BSZ) * HIDD;
            for (int idx = tid; idx < 32 * 128; idx += 256) {
                int b = idx >> 7;
                int q = (idx & 127) * 4;
                float4 v = __ldcg((const float4*)(hsrc + b * HIDD + q));
                *(float4*)&sh[b * 516 + q] = v;
            }
            __syncthreads();
            float acc[4][8];
#pragma unroll
            for (int g = 0; g < 4; ++g)
#pragma unroll
                for (int bb = 0; bb < 8; ++bb) acc[g][bb] = 0.f;
            const float* w0p = &sw[(0  + jj) * 516 + kb];
            const float* w1p = &sw[(8  + jj) * 516 + kb];
            const float* w2p = &sw[(16 + jj) * 516 + kb];
            const float* w3p = &sw[(24 + jj) * 516 + kb];
            const float* hp  = &sh[(boct * 8) * 516 + kb];
#pragma unroll 4
            for (int kk = 0; kk < 64; kk += 4) {
                float4 w0 = *(const float4*)(w0p + kk);
                float4 w1 = *(const float4*)(w1p + kk);
                float4 w2 = *(const float4*)(w2p + kk);
                float4 w3 = *(const float4*)(w3p + kk);
#pragma unroll
                for (int bb = 0; bb < 8; ++bb) {
                    float4 h = *(const float4*)(hp + bb * 516 + kk);
                    acc[0][bb] += w0.x*h.x + w0.y*h.y + w0.z*h.z + w0.w*h.w;
                    acc[1][bb] += w1.x*h.x + w1.y*h.y + w1.z*h.z + w1.w*h.w;
                    acc[2][bb] += w2.x*h.x + w2.y*h.y + w2.z*h.z + w2.w*h.w;
                    acc[3][bb] += w3.x*h.x + w3.y*h.y + w3.z*h.z + w3.w*h.w;
                }
            }
            float* rp = &red[(kseg * 32 + unit) * 32];
#pragma unroll
            for (int g = 0; g < 4; ++g)
#pragma unroll
                for (int bb = 0; bb < 8; ++bb)
                    rp[g * 8 + bb] = acc[g][bb];
            __syncthreads();
#pragma unroll
            for (int s = 0; s < 8; ++s) {
                const float* rr = &red[(s * 32 + funit) * 32];
                d0 += rr[0 * 8 + fbb];
                d1 += rr[1 * 8 + fbb];
                d2 += rr[2 * 8 + fbb];
                d3 += rr[3 * 8 + fbb];
            }
        }
        // finalize: gates = G(input proj + bias) + recurrent dot
        const float* Grow = g_G + (size_t)(fb * SEQ + t_eff) * GN + dir * G4H;
        float gi = Grow[jglob]         + d0;
        float gf = Grow[512  + jglob]  + d1;
        float gg = Grow[1024 + jglob]  + d2;
        float go = Grow[1536 + jglob]  + d3;
        float iv = sigmoidf_(gi);
        float fv = sigmoidf_(gf);
        float ov = sigmoidf_(go);
        float gv = tanhf(gg);
        c_state = fv * c_state + iv * gv;
        float hv = ov * tanhf(c_state);
        g_hbuf[(size_t)(((p ^ 1) * 2 + dir) * BSZ + fb) * HIDD + jglob] = hv;
        g_hseq[(size_t)((dir * SEQ + t_eff) * BSZ + fb) * HIDD + jglob] = hv;

        // ------- per-direction grid barrier (64 blocks, all resident) -------
        __threadfence();
        __syncthreads();
        if (tid == 0) {
            unsigned gen = g_gen[dir];
            if (atomicAdd(&g_cnt[dir], 1u) == 63u) {
                g_cnt[dir] = 0u;
                __threadfence();
                g_gen[dir] = gen + 1u;
            } else {
                while (g_gen[dir] == gen) { }
            }
            __threadfence();
        }
        __syncthreads();
        p ^= 1;
    }
}

// =====================================================================
// Kernel 3: emissions[token][tag] = concat(h_f,h_b) . lin_w[tag] + lin_b
// block = 32 tokens (same b), 256 threads, K tiled by 128 in smem.
// =====================================================================
__device__ __forceinline__ float dot4_(float4 a, float4 b) {
    return a.x * b.x + a.y * b.y + a.z * b.z + a.w * b.w;
}

__global__ __launch_bounds__(256) void emis_k(
    const float* __restrict__ lw, const float* __restrict__ lb)
{
    __shared__ float shh[32 * 132];
    __shared__ float shw[48 * 132];
    const int tid = threadIdx.x;
    const int blk = blockIdx.x;        // 0..255
    const int b = blk >> 3;
    const int s0 = (blk & 7) * 32;
    const int tt = tid & 15;           // token sub (tt, tt+16)
    const int tg = tid >> 4;           // tag group (tg, tg+16, tg+32)
    float acc[2][3] = {{0.f, 0.f, 0.f}, {0.f, 0.f, 0.f}};

    for (int kc = 0; kc < 1024; kc += 128) {
        __syncthreads();
        const int dk = kc >> 9;
        const int ko = kc & 511;
        for (int idx = tid; idx < 32 * 32; idx += 256) {
            int ti = idx >> 5;
            int q = (idx & 31) * 4;
            *(float4*)&shh[ti * 132 + q] =
                *(const float4*)&g_hseq[(size_t)((dk * SEQ + (s0 + ti)) * BSZ + b) * HIDD + ko + q];
        }
        for (int idx = tid; idx < 48 * 32; idx += 256) {
            int tag = idx >> 5;
            int q = (idx & 31) * 4;
            float4 v = make_float4(0.f, 0.f, 0.f, 0.f);
            if (tag < NTAG) v = *(const float4*)&lw[(size_t)tag * 1024 + kc + q];
            *(float4*)&shw[tag * 132 + q] = v;
        }
        __syncthreads();
#pragma unroll 8
        for (int kk = 0; kk < 128; kk += 4) {
            float4 h0 = *(const float4*)&shh[tt * 132 + kk];
            float4 h1 = *(const float4*)&shh[(tt + 16) * 132 + kk];
            float4 w0 = *(const float4*)&shw[tg * 132 + kk];
            float4 w1 = *(const float4*)&shw[(tg + 16) * 132 + kk];
            float4 w2 = *(const float4*)&shw[(tg + 32) * 132 + kk];
            acc[0][0] += dot4_(h0, w0); acc[0][1] += dot4_(h0, w1); acc[0][2] += dot4_(h0, w2);
            acc[1][0] += dot4_(h1, w0); acc[1][1] += dot4_(h1, w1); acc[1][2] += dot4_(h1, w2);
        }
    }
#pragma unroll
    for (int ti = 0; ti < 2; ++ti) {
        int token = b * SEQ + s0 + tt + ti * 16;
#pragma unroll
        for (int c = 0; c < 3; ++c) {
            int tag = tg + c * 16;
            if (tag < NTAG)
                g_em[(size_t)token * NTAG + tag] = acc[ti][c] + lb[tag];
        }
    }
}

// =====================================================================
// Kernel 4: CRF per-batch: gold score + forward algorithm (logsumexp)
// =====================================================================
__global__ __launch_bounds__(64) void crf_k(
    const int* __restrict__ tags, const float* __restrict__ st,
    const float* __restrict__ et, const float* __restrict__ tr)
{
    __shared__ float str[NTAG * NTAG];
    __shared__ float alpha[NTAG];
    __shared__ float anew[NTAG];
    __shared__ float rbuf[64];
    const int tid = threadIdx.x;
    const int b = blockIdx.x;
    const int* tg = tags + b * SEQ;

    for (int i = tid; i < NTAG * NTAG; i += 64) str[i] = tr[i];
    __syncthreads();

    // gold score partials (emission + transition terms)
    float part = 0.f;
    for (int s = tid; s < SEQ; s += 64) {
        int cur = tg[s];
        part += g_em[(size_t)(b * SEQ + s) * NTAG + cur];
        if (s + 1 < SEQ) part += str[cur * NTAG + tg[s + 1]];
    }
    rbuf[tid] = part;
    if (tid < NTAG) alpha[tid] = st[tid] + g_em[(size_t)(b * SEQ) * NTAG + tid];
    __syncthreads();

    for (int t = 1; t < SEQ; ++t) {
        if (tid < NTAG) {
            float m = -1e30f;
            for (int i = 0; i < NTAG; ++i)
                m = fmaxf(m, alpha[i] + str[i * NTAG + tid]);
            float ssum = 0.f;
            for (int i = 0; i < NTAG; ++i)
                ssum += __expf(alpha[i] + str[i * NTAG + tid] - m);
            anew[tid] = m + __logf(ssum) + g_em[(size_t)(b * SEQ + t) * NTAG + tid];
        }
        __syncthreads();
        if (tid < NTAG) alpha[tid] = anew[tid];
        __syncthreads();
    }

    if (tid == 0) {
        float sc = 0.f;
        for (int i = 0; i < 64; ++i) sc += rbuf[i];          // fixed order: deterministic
        sc += st[tg[0]] + et[tg[SEQ - 1]];
        float m = -1e30f;
        for (int j = 0; j < NTAG; ++j) m = fmaxf(m, alpha[j] + et[j]);
        float ssum = 0.f;
        for (int j = 0; j < NTAG; ++j) ssum += __expf(alpha[j] + et[j] - m);
        float logZ = m + __logf(ssum);
        g_loss[b] = logZ - sc;                               // per-sample NLL
    }
}

__global__ void final_reduce(float* __restrict__ out)
{
    if (threadIdx.x == 0) {
        float s = 0.f;
        for (int i = 0; i < BSZ; ++i) s += g_loss[i];
        out[0] = s / (float)BSZ;
    }
}

// =====================================================================
extern "C" void kernel_launch(void* const* d_in, const int* in_sizes, int n_in,
                              void* d_out, int out_size)
{
    (void)in_sizes; (void)n_in; (void)out_size;
    const int*   x   = (const int*)d_in[0];
    const int*   tgs = (const int*)d_in[1];
    const float* emb = (const float*)d_in[2];
    const float* wif = (const float*)d_in[3];
    const float* whf = (const float*)d_in[4];
    const float* bf  = (const float*)d_in[5];
    const float* wib = (const float*)d_in[6];
    const float* whb = (const float*)d_in[7];
    const float* bb  = (const float*)d_in[8];
    const float* lw  = (const float*)d_in[9];
    const float* lb  = (const float*)d_in[10];
    const float* st  = (const float*)d_in[11];
    const float* et  = (const float*)d_in[12];
    const float* tr  = (const float*)d_in[13];
    float* out = (float*)d_out;

    const int rec_smem = (32 * 516 + 32 * 516 + 8 * 32 * 32) * 4;  // 164864 B
    cudaFuncSetAttribute(lstm_rec, cudaFuncAttributeMaxDynamicSharedMemorySize, rec_smem);

    dim3 gemm_grid(32, 64);
    gemm_in<<<gemm_grid, 256>>>(x, emb, wif, wib, bf, bb);
    lstm_rec<<<128, 256, rec_smem>>>(whf, whb);
    emis_k<<<256, 256>>>(lw, lb);
    crf_k<<<BSZ, 64>>>(tgs, st, et, tr);
    final_reduce<<<1, 32>>>(out);
}

// round 2
// speedup vs baseline: 1.3051x; 1.3051x over previous
#include <cuda_runtime.h>
#include <cstdint>
#include <cstddef>

#define BSZ 32
#define SEQ 256
#define EMBD 256
#define HIDD 512
#define NTAG 45
#define NTOK (BSZ*SEQ)     // 8192
#define G4H  2048          // 4*HID
#define GN   4096          // both directions

// ---------------- scratch (static device allocations; no cudaMalloc) ----------------
__device__ __align__(16) float g_G[(size_t)NTOK * GN];           // input proj + bias, [token][4096]
__device__ __align__(16) float g_hseq[2 * SEQ * BSZ * HIDD];     // [dir][t][b][h]
__device__ __align__(16) float g_hbuf[2 * 2 * BSZ * HIDD];       // [phase][dir][b][h]
__device__ __align__(16) float g_em[(size_t)NTOK * NTAG];        // emissions [token][tag]
__device__ float g_loss[BSZ];
__device__ unsigned g_cnt4[4 * 32];                              // padded barrier slots: (dir*2+grp)*32
__device__ unsigned g_gen4[4 * 32];

// =====================================================================
// Kernel 1: G[token][n] = dot(emb[x[token]], W[n]) + bias[n]
// =====================================================================
__global__ __launch_bounds__(256) void gemm_in(
    const int* __restrict__ x, const float* __restrict__ emb,
    const float* __restrict__ wf, const float* __restrict__ wb,
    const float* __restrict__ bf, const float* __restrict__ bb)
{
    __shared__ float sA[16 * 132];
    __shared__ float sW[16 * 132];
    const int tid = threadIdx.x;
    const int bx = blockIdx.x;   // n tile (0..31)
    const int by = blockIdx.y;   // m tile (0..63)
    const int tx = tid & 15, ty = tid >> 4;

    float acc[8][8];
#pragma unroll
    for (int i = 0; i < 8; ++i)
#pragma unroll
        for (int j = 0; j < 8; ++j) acc[i][j] = 0.f;

    const int f4a = tid * 2, f4b = tid * 2 + 1;
    const int ra = f4a >> 2, qa = (f4a & 3) * 4;
    const int rb = f4b >> 2, qb = (f4b & 3) * 4;
    const float* arow_a = emb + (size_t)x[by * 128 + ra] * EMBD;
    const float* arow_b = emb + (size_t)x[by * 128 + rb] * EMBD;
    const int na = bx * 128 + ra, nb = bx * 128 + rb;
    const float* wrow_a = (na < G4H) ? (wf + (size_t)na * EMBD) : (wb + (size_t)(na - G4H) * EMBD);
    const float* wrow_b = (nb < G4H) ? (wf + (size_t)nb * EMBD) : (wb + (size_t)(nb - G4H) * EMBD);

    for (int kb = 0; kb < EMBD; kb += 16) {
        __syncthreads();
        float4 va = *(const float4*)(arow_a + kb + qa);
        float4 vb = *(const float4*)(arow_b + kb + qb);
        float4 wa = *(const float4*)(wrow_a + kb + qa);
        float4 wv = *(const float4*)(wrow_b + kb + qb);
        sA[(qa + 0) * 132 + ra] = va.x; sA[(qa + 1) * 132 + ra] = va.y;
        sA[(qa + 2) * 132 + ra] = va.z; sA[(qa + 3) * 132 + ra] = va.w;
        sA[(qb + 0) * 132 + rb] = vb.x; sA[(qb + 1) * 132 + rb] = vb.y;
        sA[(qb + 2) * 132 + rb] = vb.z; sA[(qb + 3) * 132 + rb] = vb.w;
        sW[(qa + 0) * 132 + ra] = wa.x; sW[(qa + 1) * 132 + ra] = wa.y;
        sW[(qa + 2) * 132 + ra] = wa.z; sW[(qa + 3) * 132 + ra] = wa.w;
        sW[(qb + 0) * 132 + rb] = wv.x; sW[(qb + 1) * 132 + rb] = wv.y;
        sW[(qb + 2) * 132 + rb] = wv.z; sW[(qb + 3) * 132 + rb] = wv.w;
        __syncthreads();
#pragma unroll
        for (int kk = 0; kk < 16; ++kk) {
            float4 a0 = *(const float4*)&sA[kk * 132 + ty * 8];
            float4 a1 = *(const float4*)&sA[kk * 132 + ty * 8 + 4];
            float4 b0 = *(const float4*)&sW[kk * 132 + tx * 8];
            float4 b1 = *(const float4*)&sW[kk * 132 + tx * 8 + 4];
            float av[8] = {a0.x, a0.y, a0.z, a0.w, a1.x, a1.y, a1.z, a1.w};
            float bv[8] = {b0.x, b0.y, b0.z, b0.w, b1.x, b1.y, b1.z, b1.w};
#pragma unroll
            for (int i = 0; i < 8; ++i)
#pragma unroll
                for (int j = 0; j < 8; ++j)
                    acc[i][j] += av[i] * bv[j];
        }
    }
    const int m0 = by * 128 + ty * 8;
    const int n0 = bx * 128 + tx * 8;
#pragma unroll
    for (int i = 0; i < 8; ++i) {
        float* dst = g_G + (size_t)(m0 + i) * GN + n0;
#pragma unroll
        for (int j = 0; j < 8; ++j) {
            int n = n0 + j;
            float bias = (n < G4H) ? bf[n] : bb[n - G4H];
            dst[j] = acc[i][j] + bias;
        }
    }
}

// =====================================================================
// Kernel 2: persistent bidirectional LSTM recurrence (pipelined 2 groups)
// 128 blocks (64/dir), 256 threads, 1/SM. Block owns 8 hidden j.
// Per step, batches split into groups {0..15},{16..31} with separate
// barriers: group B's compute hides group A's barrier latency.
// =====================================================================
__device__ __forceinline__ float sigmoidf_(float v) { return 1.f / (1.f + __expf(-v)); }

__global__ __launch_bounds__(256) void lstm_rec(
    const float* __restrict__ whf, const float* __restrict__ whb)
{
    extern __shared__ float smem[];
    float* sw  = smem;                 // 32 rows x 516 (row = g*8+jj)
    float* sh  = smem + 32 * 516;      // 16 rows x 516 (row = batch-in-group)
    float* red = smem + 48 * 516;      // [16 kseg][16 unit] x 36 (padded)

    const int tid = threadIdx.x;
    const int dir = blockIdx.x >> 6;   // 0 fwd, 1 bwd
    const int blk = blockIdx.x & 63;
    const int jbase = blk * 8;
    const float* whh = dir ? whb : whf;

    // load owned w_hh rows: 32 rows x 512 floats
    for (int idx = tid; idx < 32 * 128; idx += 256) {
        int row = idx >> 7;
        int q = (idx & 127) * 4;
        int g = row >> 3, j = row & 7;
        *(float4*)&sw[row * 516 + q] =
            *(const float4*)(whh + (size_t)(g * 512 + jbase + j) * HIDD + q);
    }

    // dot-phase decomposition: 16 ksegs x 16 units
    const int kseg = tid >> 4;          // 0..15 (32 k each)
    const int unit = tid & 15;
    const int jj = unit & 7;            // hidden sub-index
    const int bo = unit >> 3;           // batch-octet within group
    const int kb = kseg * 32;

    // finalize decomposition: thread owns (fj, fb); warps 0-3 = group 0
    const int fj = tid & 7;             // hidden sub-index
    const int fb = tid >> 3;            // batch 0..31
    const int jglob = jbase + fj;
    const int fgrp = fb >> 4;
    const int fbl = fb & 15;
    const int funit = fj + (fbl >> 3) * 8;
    const int fbb = fbl & 7;

    // barrier base generations (read before this block's first arrive)
    unsigned gb0 = 0, gb1 = 0;
    if (tid == 0) {
        gb0 = *(volatile unsigned*)&g_gen4[(dir * 2 + 0) * 32];
        gb1 = *(volatile unsigned*)&g_gen4[(dir * 2 + 1) * 32];
    }

    float c_state = 0.f;
    int p = 0;
    __syncthreads();

    for (int t = 0; t < SEQ; ++t) {
        const int t_eff = dir ? (SEQ - 1 - t) : t;
        // prefetch input-projection gate values (independent of barriers)
        const float* Grow = g_G + (size_t)(fb * SEQ + t_eff) * GN + dir * G4H;
        float pg0 = __ldg(Grow + jglob);
        float pg1 = __ldg(Grow + 512 + jglob);
        float pg2 = __ldg(Grow + 1024 + jglob);
        float pg3 = __ldg(Grow + 1536 + jglob);

#pragma unroll
        for (int grp = 0; grp < 2; ++grp) {
            const int slot = (dir * 2 + grp) * 32;
            float d0 = 0.f, d1 = 0.f, d2 = 0.f, d3 = 0.f;
            if (t > 0) {
                // wait for all blocks' h of this group at step t-1
                if (tid == 0) {
                    unsigned base = grp ? gb1 : gb0;
                    while ((unsigned)(*(volatile unsigned*)&g_gen4[slot] - base) < (unsigned)t) { }
                    __threadfence();
                }
                __syncthreads();
                // stage h_prev for this group's 16 batches (L2)
                const float* hsrc = g_hbuf + (size_t)((p * 2 + dir) * BSZ + grp * 16) * HIDD;
                for (int idx = tid; idx < 16 * 128; idx += 256) {
                    int b = idx >> 7;
                    int q = (idx & 127) * 4;
                    float4 v = __ldcg((const float4*)(hsrc + b * HIDD + q));
                    *(float4*)&sh[b * 516 + q] = v;
                }
                __syncthreads();
                // dot: 32 gate-rows x 16 batches x 512 k, ksplit 16
                float acc[4][8];
#pragma unroll
                for (int g = 0; g < 4; ++g)
#pragma unroll
                    for (int bb = 0; bb < 8; ++bb) acc[g][bb] = 0.f;
                const float* w0p = &sw[jj * 516 + kb];
                const float* w1p = w0p + 8 * 516;
                const float* w2p = w0p + 16 * 516;
                const float* w3p = w0p + 24 * 516;
                const float* hp  = &sh[(bo * 8) * 516 + kb];
#pragma unroll
                for (int kk = 0; kk < 32; kk += 4) {
                    float4 w0 = *(const float4*)(w0p + kk);
                    float4 w1 = *(const float4*)(w1p + kk);
                    float4 w2 = *(const float4*)(w2p + kk);
                    float4 w3 = *(const float4*)(w3p + kk);
#pragma unroll
                    for (int bb = 0; bb < 8; ++bb) {
                        float4 h = *(const float4*)(hp + bb * 516 + kk);
                        acc[0][bb] += w0.x*h.x + w0.y*h.y + w0.z*h.z + w0.w*h.w;
                        acc[1][bb] += w1.x*h.x + w1.y*h.y + w1.z*h.z + w1.w*h.w;
                        acc[2][bb] += w2.x*h.x + w2.y*h.y + w2.z*h.z + w2.w*h.w;
                        acc[3][bb] += w3.x*h.x + w3.y*h.y + w3.z*h.z + w3.w*h.w;
                    }
                }
                float* rp = &red[(kseg * 16 + unit) * 36];
#pragma unroll
                for (int g = 0; g < 4; ++g) {
                    *(float4*)&rp[g * 8]     = make_float4(acc[g][0], acc[g][1], acc[g][2], acc[g][3]);
                    *(float4*)&rp[g * 8 + 4] = make_float4(acc[g][4], acc[g][5], acc[g][6], acc[g][7]);
                }
                __syncthreads();
                if (fgrp == grp) {
#pragma unroll
                    for (int s = 0; s < 16; ++s) {
                        const float* rr = &red[(s * 16 + funit) * 36];
                        d0 += rr[fbb];
                        d1 += rr[8 + fbb];
                        d2 += rr[16 + fbb];
                        d3 += rr[24 + fbb];
                    }
                }
            }
            // finalize for this group's threads
            if (fgrp == grp) {
                float gi = pg0 + d0;
                float gf = pg1 + d1;
                float gg = pg2 + d2;
                float go = pg3 + d3;
                float iv = sigmoidf_(gi);
                float fv = sigmoidf_(gf);
                float ov = sigmoidf_(go);
                float gv = tanhf(gg);
                c_state = fv * c_state + iv * gv;
                float hv = ov * tanhf(c_state);
                g_hbuf[(size_t)(((p ^ 1) * 2 + dir) * BSZ + fb) * HIDD + jglob] = hv;
                g_hseq[(size_t)((dir * SEQ + t_eff) * BSZ + fb) * HIDD + jglob] = hv;
            }
            __threadfence();
            __syncthreads();
            if (tid == 0) {
                if (atomicAdd(&g_cnt4[slot], 1u) == 63u) {
                    g_cnt4[slot] = 0u;
                    __threadfence();
                    *(volatile unsigned*)&g_gen4[slot] =
                        *(volatile unsigned*)&g_gen4[slot] + 1u;
                }
            }
        }
        p ^= 1;
    }
}

// =====================================================================
// Kernel 3: emissions[token][tag] = concat(h_f,h_b) . lin_w[tag] + lin_b
// =====================================================================
__device__ __forceinline__ float dot4_(float4 a, float4 b) {
    return a.x * b.x + a.y * b.y + a.z * b.z + a.w * b.w;
}

__global__ __launch_bounds__(256) void emis_k(
    const float* __restrict__ lw, const float* __restrict__ lb)
{
    __shared__ float shh[32 * 132];
    __shared__ float shw[48 * 132];
    const int tid = threadIdx.x;
    const int blk = blockIdx.x;        // 0..255
    const int b = blk >> 3;
    const int s0 = (blk & 7) * 32;
    const int tt = tid & 15;
    const int tg = tid >> 4;
    float acc[2][3] = {{0.f, 0.f, 0.f}, {0.f, 0.f, 0.f}};

    for (int kc = 0; kc < 1024; kc += 128) {
        __syncthreads();
        const int dk = kc >> 9;
        const int ko = kc & 511;
        for (int idx = tid; idx < 32 * 32; idx += 256) {
            int ti = idx >> 5;
            int q = (idx & 31) * 4;
            *(float4*)&shh[ti * 132 + q] =
                *(const float4*)&g_hseq[(size_t)((dk * SEQ + (s0 + ti)) * BSZ + b) * HIDD + ko + q];
        }
        for (int idx = tid; idx < 48 * 32; idx += 256) {
            int tag = idx >> 5;
            int q = (idx & 31) * 4;
            float4 v = make_float4(0.f, 0.f, 0.f, 0.f);
            if (tag < NTAG) v = *(const float4*)&lw[(size_t)tag * 1024 + kc + q];
            *(float4*)&shw[tag * 132 + q] = v;
        }
        __syncthreads();
#pragma unroll 8
        for (int kk = 0; kk < 128; kk += 4) {
            float4 h0 = *(const float4*)&shh[tt * 132 + kk];
            float4 h1 = *(const float4*)&shh[(tt + 16) * 132 + kk];
            float4 w0 = *(const float4*)&shw[tg * 132 + kk];
            float4 w1 = *(const float4*)&shw[(tg + 16) * 132 + kk];
            float4 w2 = *(const float4*)&shw[(tg + 32) * 132 + kk];
            acc[0][0] += dot4_(h0, w0); acc[0][1] += dot4_(h0, w1); acc[0][2] += dot4_(h0, w2);
            acc[1][0] += dot4_(h1, w0); acc[1][1] += dot4_(h1, w1); acc[1][2] += dot4_(h1, w2);
        }
    }
#pragma unroll
    for (int ti = 0; ti < 2; ++ti) {
        int token = b * SEQ + s0 + tt + ti * 16;
#pragma unroll
        for (int c = 0; c < 3; ++c) {
            int tag = tg + c * 16;
            if (tag < NTAG)
                g_em[(size_t)token * NTAG + tag] = acc[ti][c] + lb[tag];
        }
    }
}

// =====================================================================
// Kernel 4: CRF — gold score + forward algorithm, exp-domain mat-vec.
// Precompute E=exp(trans) per-column in registers: 45 exps/step instead
// of 2025 MUFU ops.
// =====================================================================
__global__ __launch_bounds__(64) void crf_k(
    const int* __restrict__ tags, const float* __restrict__ st,
    const float* __restrict__ et, const float* __restrict__ tr)
{
    __shared__ float str[NTAG * NTAG];
    __shared__ float alpha[NTAG];
    __shared__ float ea[NTAG];
    __shared__ float rbuf[64];
    const int tid = threadIdx.x;
    const int b = blockIdx.x;
    const int* tg = tags + b * SEQ;

    for (int i = tid; i < NTAG * NTAG; i += 64) str[i] = tr[i];
    __syncthreads();

    float Ecol[NTAG];
    if (tid < NTAG) {
#pragma unroll
        for (int i = 0; i < NTAG; ++i) Ecol[i] = __expf(str[i * NTAG + tid]);
    }

    // gold score partials (emission + transition terms)
    float part = 0.f;
    for (int s = tid; s < SEQ; s += 64) {
        int cur = tg[s];
        part += g_em[(size_t)(b * SEQ + s) * NTAG + cur];
        if (s + 1 < SEQ) part += str[cur * NTAG + tg[s + 1]];
    }
    rbuf[tid] = part;
    if (tid < NTAG) alpha[tid] = st[tid] + g_em[(size_t)(b * SEQ) * NTAG + tid];
    __syncthreads();

    for (int t = 1; t < SEQ; ++t) {
        float m = -1e30f;
        if (tid < NTAG) {
#pragma unroll 5
            for (int i = 0; i < NTAG; ++i) m = fmaxf(m, alpha[i]);
            ea[tid] = __expf(alpha[tid] - m);
        }
        __syncthreads();
        if (tid < NTAG) {
            float ssum = 0.f;
#pragma unroll 5
            for (int i = 0; i < NTAG; ++i) ssum += Ecol[i] * ea[i];
            alpha[tid] = m + __logf(ssum) + g_em[(size_t)(b * SEQ + t) * NTAG + tid];
        }
        __syncthreads();
    }

    if (tid == 0) {
        float sc = 0.f;
        for (int i = 0; i < 64; ++i) sc += rbuf[i];          // fixed order: deterministic
        sc += st[tg[0]] + et[tg[SEQ - 1]];
        float m = -1e30f;
        for (int j = 0; j < NTAG; ++j) m = fmaxf(m, alpha[j] + et[j]);
        float ssum = 0.f;
        for (int j = 0; j < NTAG; ++j) ssum += __expf(alpha[j] + et[j] - m);
        float logZ = m + __logf(ssum);
        g_loss[b] = logZ - sc;                               // per-sample NLL
    }
}

__global__ void final_reduce(float* __restrict__ out)
{
    if (threadIdx.x == 0) {
        float s = 0.f;
        for (int i = 0; i < BSZ; ++i) s += g_loss[i];
        out[0] = s / (float)BSZ;
    }
}

// =====================================================================
extern "C" void kernel_launch(void* const* d_in, const int* in_sizes, int n_in,
                              void* d_out, int out_size)
{
    (void)in_sizes; (void)n_in; (void)out_size;
    const int*   x   = (const int*)d_in[0];
    const int*   tgs = (const int*)d_in[1];
    const float* emb = (const float*)d_in[2];
    const float* wif = (const float*)d_in[3];
    const float* whf = (const float*)d_in[4];
    const float* bf  = (const float*)d_in[5];
    const float* wib = (const float*)d_in[6];
    const float* whb = (const float*)d_in[7];
    const float* bb  = (const float*)d_in[8];
    const float* lw  = (const float*)d_in[9];
    const float* lb  = (const float*)d_in[10];
    const float* st  = (const float*)d_in[11];
    const float* et  = (const float*)d_in[12];
    const float* tr  = (const float*)d_in[13];
    float* out = (float*)d_out;

    const int rec_smem = (32 * 516 + 16 * 516 + 256 * 36) * 4;  // 135936 B
    cudaFuncSetAttribute(lstm_rec, cudaFuncAttributeMaxDynamicSharedMemorySize, rec_smem);

    dim3 gemm_grid(32, 64);
    gemm_in<<<gemm_grid, 256>>>(x, emb, wif, wib, bf, bb);
    lstm_rec<<<128, 256, rec_smem>>>(whf, whb);
    emis_k<<<256, 256>>>(lw, lb);
    crf_k<<<BSZ, 64>>>(tgs, st, et, tr);
    final_reduce<<<1, 32>>>(out);
}

// round 3
// speedup vs baseline: 1.3970x; 1.0704x over previous
#include <cuda_runtime.h>
#include <cstdint>
#include <cstddef>

#define BSZ 32
#define SEQ 256
#define EMBD 256
#define HIDD 512
#define NTAG 45
#define NTOK (BSZ*SEQ)     // 8192
#define G4H  2048          // 4*HID
#define GN   4096          // both directions
#define RS   572           // smem row stride (floats): RS%4==0, RS%32==28 -> jj*RS banks distinct

// ---------------- scratch (static device allocations; no cudaMalloc) ----------------
__device__ __align__(16) float g_G[(size_t)NTOK * GN];           // input proj + bias, [token][4096]
__device__ __align__(16) float g_hseq[2 * SEQ * BSZ * HIDD];     // [dir][t][b][h]
__device__ __align__(16) float g_hbuf[2 * 2 * BSZ * HIDD];       // [phase][dir][b][h]
__device__ __align__(16) float g_em[(size_t)NTOK * NTAG];        // emissions [token][tag]
__device__ float g_loss[BSZ];
__device__ unsigned g_cnt4[4 * 32];                              // padded barrier slots
__device__ unsigned g_gen4[4 * 32];

// =====================================================================
// Kernel 1: G[token][n] = dot(emb[x[token]], W[n]) + bias[n]
// =====================================================================
__global__ __launch_bounds__(256) void gemm_in(
    const int* __restrict__ x, const float* __restrict__ emb,
    const float* __restrict__ wf, const float* __restrict__ wb,
    const float* __restrict__ bf, const float* __restrict__ bb)
{
    __shared__ float sA[16 * 132];
    __shared__ float sW[16 * 132];
    const int tid = threadIdx.x;
    const int bx = blockIdx.x;   // n tile (0..31)
    const int by = blockIdx.y;   // m tile (0..63)
    const int tx = tid & 15, ty = tid >> 4;

    float acc[8][8];
#pragma unroll
    for (int i = 0; i < 8; ++i)
#pragma unroll
        for (int j = 0; j < 8; ++j) acc[i][j] = 0.f;

    const int f4a = tid * 2, f4b = tid * 2 + 1;
    const int ra = f4a >> 2, qa = (f4a & 3) * 4;
    const int rb = f4b >> 2, qb = (f4b & 3) * 4;
    const float* arow_a = emb + (size_t)x[by * 128 + ra] * EMBD;
    const float* arow_b = emb + (size_t)x[by * 128 + rb] * EMBD;
    const int na = bx * 128 + ra, nb = bx * 128 + rb;
    const float* wrow_a = (na < G4H) ? (wf + (size_t)na * EMBD) : (wb + (size_t)(na - G4H) * EMBD);
    const float* wrow_b = (nb < G4H) ? (wf + (size_t)nb * EMBD) : (wb + (size_t)(nb - G4H) * EMBD);

    for (int kb = 0; kb < EMBD; kb += 16) {
        __syncthreads();
        float4 va = *(const float4*)(arow_a + kb + qa);
        float4 vb = *(const float4*)(arow_b + kb + qb);
        float4 wa = *(const float4*)(wrow_a + kb + qa);
        float4 wv = *(const float4*)(wrow_b + kb + qb);
        sA[(qa + 0) * 132 + ra] = va.x; sA[(qa + 1) * 132 + ra] = va.y;
        sA[(qa + 2) * 132 + ra] = va.z; sA[(qa + 3) * 132 + ra] = va.w;
        sA[(qb + 0) * 132 + rb] = vb.x; sA[(qb + 1) * 132 + rb] = vb.y;
        sA[(qb + 2) * 132 + rb] = vb.z; sA[(qb + 3) * 132 + rb] = vb.w;
        sW[(qa + 0) * 132 + ra] = wa.x; sW[(qa + 1) * 132 + ra] = wa.y;
        sW[(qa + 2) * 132 + ra] = wa.z; sW[(qa + 3) * 132 + ra] = wa.w;
        sW[(qb + 0) * 132 + rb] = wv.x; sW[(qb + 1) * 132 + rb] = wv.y;
        sW[(qb + 2) * 132 + rb] = wv.z; sW[(qb + 3) * 132 + rb] = wv.w;
        __syncthreads();
#pragma unroll
        for (int kk = 0; kk < 16; ++kk) {
            float4 a0 = *(const float4*)&sA[kk * 132 + ty * 8];
            float4 a1 = *(const float4*)&sA[kk * 132 + ty * 8 + 4];
            float4 b0 = *(const float4*)&sW[kk * 132 + tx * 8];
            float4 b1 = *(const float4*)&sW[kk * 132 + tx * 8 + 4];
            float av[8] = {a0.x, a0.y, a0.z, a0.w, a1.x, a1.y, a1.z, a1.w};
            float bv[8] = {b0.x, b0.y, b0.z, b0.w, b1.x, b1.y, b1.z, b1.w};
#pragma unroll
            for (int i = 0; i < 8; ++i)
#pragma unroll
                for (int j = 0; j < 8; ++j)
                    acc[i][j] += av[i] * bv[j];
        }
    }
    const int m0 = by * 128 + ty * 8;
    const int n0 = bx * 128 + tx * 8;
#pragma unroll
    for (int i = 0; i < 8; ++i) {
        float* dst = g_G + (size_t)(m0 + i) * GN + n0;
#pragma unroll
        for (int j = 0; j < 8; ++j) {
            int n = n0 + j;
            float bias = (n < G4H) ? bf[n] : bb[n - G4H];
            dst[j] = acc[i][j] + bias;
        }
    }
}

// =====================================================================
// Kernel 2: persistent bidirectional LSTM recurrence — conflict-free.
// 128 blocks (64/dir), 256 threads, 1/SM. Block owns 8 hidden j.
// 2 batch-groups pipelined to hide barrier latency.
// smem layout (k-swizzled): element k stored at k + 4*(k>>5);
// row stride RS=572 (=28 mod 32 -> distinct banks across jj rows).
// lane map in dot: unit = jj + 8*bo -> h loads are phase-broadcast.
// =====================================================================
__device__ __forceinline__ float sigmoidf_(float v) { return 1.f / (1.f + __expf(-v)); }

__global__ __launch_bounds__(256) void lstm_rec(
    const float* __restrict__ whf, const float* __restrict__ whb)
{
    extern __shared__ float smem[];
    float* sw  = smem;                 // 32 rows x RS (row = g*8+jj)
    float* sh  = smem + 32 * RS;       // 16 rows x RS (row = batch-in-group)
    float* red = smem + 48 * RS;       // [16 kseg][16 unit] x 36

    const int tid = threadIdx.x;
    const int dir = blockIdx.x >> 6;   // 0 fwd, 1 bwd
    const int blk = blockIdx.x & 63;
    const int jbase = blk * 8;
    const float* whh = dir ? whb : whf;

    // load owned w_hh rows: 32 rows x 512 floats, with k-swizzle
    for (int idx = tid; idx < 32 * 128; idx += 256) {
        int row = idx >> 7;            // g*8 + j
        int q4 = idx & 127;
        int g = row >> 3, j = row & 7;
        float4 v = *(const float4*)(whh + (size_t)(g * 512 + jbase + j) * HIDD + q4 * 4);
        *(float4*)&sw[row * RS + q4 * 4 + 4 * (q4 >> 3)] = v;
    }

    // dot decomposition: 16 ksegs x 16 units; unit = jj + 8*bo
    const int kseg = tid >> 4;          // 0..15 (32 k each)
    const int unit = tid & 15;
    const int jj = unit & 7;
    const int bo = unit >> 3;           // 0..1 (8 batches each)
    const int kb = kseg * 36;           // swizzled k base

    // finalize decomposition: thread owns (fj, fb)
    const int fj = tid & 7;
    const int fb = tid >> 3;            // 0..31
    const int jglob = jbase + fj;
    const int fgrp = fb >> 4;
    const int fbl = fb & 15;
    const int funit = fj + 8 * (fbl >> 3);
    const int fbb = fbl & 7;

    unsigned gb0 = 0, gb1 = 0;
    if (tid == 0) {
        gb0 = *(volatile unsigned*)&g_gen4[(dir * 2 + 0) * 32];
        gb1 = *(volatile unsigned*)&g_gen4[(dir * 2 + 1) * 32];
    }

    float c_state = 0.f;
    int p = 0;
    __syncthreads();

    for (int t = 0; t < SEQ; ++t) {
        const int t_eff = dir ? (SEQ - 1 - t) : t;
        const float* Grow = g_G + (size_t)(fb * SEQ + t_eff) * GN + dir * G4H;
        float pg0 = __ldg(Grow + jglob);
        float pg1 = __ldg(Grow + 512 + jglob);
        float pg2 = __ldg(Grow + 1024 + jglob);
        float pg3 = __ldg(Grow + 1536 + jglob);

#pragma unroll
        for (int grp = 0; grp < 2; ++grp) {
            const int slot = (dir * 2 + grp) * 32;
            float d0 = 0.f, d1 = 0.f, d2 = 0.f, d3 = 0.f;
            if (t > 0) {
                if (tid == 0) {
                    unsigned base = grp ? gb1 : gb0;
                    while ((unsigned)(*(volatile unsigned*)&g_gen4[slot] - base) < (unsigned)t) { }
                    __threadfence();
                }
                __syncthreads();
                // stage h_prev (group's 16 batches), k-swizzled
                const float* hsrc = g_hbuf + (size_t)((p * 2 + dir) * BSZ + grp * 16) * HIDD;
                for (int idx = tid; idx < 16 * 128; idx += 256) {
                    int b = idx >> 7;
                    int q4 = idx & 127;
                    float4 v = __ldcg((const float4*)(hsrc + b * HIDD + q4 * 4));
                    *(float4*)&sh[b * RS + q4 * 4 + 4 * (q4 >> 3)] = v;
                }
                __syncthreads();
                float acc[4][8];
#pragma unroll
                for (int g = 0; g < 4; ++g)
#pragma unroll
                    for (int bb = 0; bb < 8; ++bb) acc[g][bb] = 0.f;
                const float* w0p = &sw[jj * RS + kb];
                const float* w1p = w0p + 8 * RS;
                const float* w2p = w0p + 16 * RS;
                const float* w3p = w0p + 24 * RS;
                const float* hp  = &sh[(bo * 8) * RS + kb];
#pragma unroll
                for (int kk = 0; kk < 32; kk += 4) {
                    float4 w0 = *(const float4*)(w0p + kk);
                    float4 w1 = *(const float4*)(w1p + kk);
                    float4 w2 = *(const float4*)(w2p + kk);
                    float4 w3 = *(const float4*)(w3p + kk);
#pragma unroll
                    for (int bb = 0; bb < 8; ++bb) {
                        float4 h = *(const float4*)(hp + bb * RS + kk);
                        acc[0][bb] += w0.x*h.x + w0.y*h.y + w0.z*h.z + w0.w*h.w;
                        acc[1][bb] += w1.x*h.x + w1.y*h.y + w1.z*h.z + w1.w*h.w;
                        acc[2][bb] += w2.x*h.x + w2.y*h.y + w2.z*h.z + w2.w*h.w;
                        acc[3][bb] += w3.x*h.x + w3.y*h.y + w3.z*h.z + w3.w*h.w;
                    }
                }
                float* rp = &red[(kseg * 16 + unit) * 36];
#pragma unroll
                for (int g = 0; g < 4; ++g) {
                    *(float4*)&rp[g * 8]     = make_float4(acc[g][0], acc[g][1], acc[g][2], acc[g][3]);
                    *(float4*)&rp[g * 8 + 4] = make_float4(acc[g][4], acc[g][5], acc[g][6], acc[g][7]);
                }
                __syncthreads();
                if (fgrp == grp) {
#pragma unroll
                    for (int s = 0; s < 16; ++s) {
                        const float* rr = &red[(s * 16 + funit) * 36];
                        d0 += rr[fbb];
                        d1 += rr[8 + fbb];
                        d2 += rr[16 + fbb];
                        d3 += rr[24 + fbb];
                    }
                }
            }
            if (fgrp == grp) {
                float gi = pg0 + d0;
                float gf = pg1 + d1;
                float gg = pg2 + d2;
                float go = pg3 + d3;
                float iv = sigmoidf_(gi);
                float fv = sigmoidf_(gf);
                float ov = sigmoidf_(go);
                float gv = tanhf(gg);
                c_state = fv * c_state + iv * gv;
                float hv = ov * tanhf(c_state);
                g_hbuf[(size_t)(((p ^ 1) * 2 + dir) * BSZ + fb) * HIDD + jglob] = hv;
                g_hseq[(size_t)((dir * SEQ + t_eff) * BSZ + fb) * HIDD + jglob] = hv;
            }
            __threadfence();
            __syncthreads();
            if (tid == 0) {
                if (atomicAdd(&g_cnt4[slot], 1u) == 63u) {
                    g_cnt4[slot] = 0u;
                    __threadfence();
                    *(volatile unsigned*)&g_gen4[slot] =
                        *(volatile unsigned*)&g_gen4[slot] + 1u;
                }
            }
        }
        p ^= 1;
    }
}

// =====================================================================
// Kernel 3: emissions[token][tag] = concat(h_f,h_b) . lin_w[tag] + lin_b
// =====================================================================
__device__ __forceinline__ float dot4_(float4 a, float4 b) {
    return a.x * b.x + a.y * b.y + a.z * b.z + a.w * b.w;
}

__global__ __launch_bounds__(256) void emis_k(
    const float* __restrict__ lw, const float* __restrict__ lb)
{
    __shared__ float shh[32 * 132];
    __shared__ float shw[48 * 132];
    const int tid = threadIdx.x;
    const int blk = blockIdx.x;        // 0..255
    const int b = blk >> 3;
    const int s0 = (blk & 7) * 32;
    const int tt = tid & 15;
    const int tg = tid >> 4;
    float acc[2][3] = {{0.f, 0.f, 0.f}, {0.f, 0.f, 0.f}};

    for (int kc = 0; kc < 1024; kc += 128) {
        __syncthreads();
        const int dk = kc >> 9;
        const int ko = kc & 511;
        for (int idx = tid; idx < 32 * 32; idx += 256) {
            int ti = idx >> 5;
            int q = (idx & 31) * 4;
            *(float4*)&shh[ti * 132 + q] =
                *(const float4*)&g_hseq[(size_t)((dk * SEQ + (s0 + ti)) * BSZ + b) * HIDD + ko + q];
        }
        for (int idx = tid; idx < 48 * 32; idx += 256) {
            int tag = idx >> 5;
            int q = (idx & 31) * 4;
            float4 v = make_float4(0.f, 0.f, 0.f, 0.f);
            if (tag < NTAG) v = *(const float4*)&lw[(size_t)tag * 1024 + kc + q];
            *(float4*)&shw[tag * 132 + q] = v;
        }
        __syncthreads();
#pragma unroll 8
        for (int kk = 0; kk < 128; kk += 4) {
            float4 h0 = *(const float4*)&shh[tt * 132 + kk];
            float4 h1 = *(const float4*)&shh[(tt + 16) * 132 + kk];
            float4 w0 = *(const float4*)&shw[tg * 132 + kk];
            float4 w1 = *(const float4*)&shw[(tg + 16) * 132 + kk];
            float4 w2 = *(const float4*)&shw[(tg + 32) * 132 + kk];
            acc[0][0] += dot4_(h0, w0); acc[0][1] += dot4_(h0, w1); acc[0][2] += dot4_(h0, w2);
            acc[1][0] += dot4_(h1, w0); acc[1][1] += dot4_(h1, w1); acc[1][2] += dot4_(h1, w2);
        }
    }
#pragma unroll
    for (int ti = 0; ti < 2; ++ti) {
        int token = b * SEQ + s0 + tt + ti * 16;
#pragma unroll
        for (int c = 0; c < 3; ++c) {
            int tag = tg + c * 16;
            if (tag < NTAG)
                g_em[(size_t)token * NTAG + tag] = acc[ti][c] + lb[tag];
        }
    }
}

// =====================================================================
// Kernel 4: CRF — gold score + forward algorithm.
// exp(trans) kept in SHARED (stride 48, conflict-free), ping-pong alpha,
// 2 syncs/step. No register-indexed arrays (avoids local-mem spills).
// =====================================================================
__global__ __launch_bounds__(64) void crf_k(
    const int* __restrict__ tags, const float* __restrict__ st,
    const float* __restrict__ et, const float* __restrict__ tr)
{
    __shared__ float str[NTAG * NTAG];
    __shared__ float sE[NTAG * 48];
    __shared__ float ab[2][48];
    __shared__ float ea[48];
    __shared__ float rbuf[64];
    const int tid = threadIdx.x;
    const int b = blockIdx.x;
    const int* tg = tags + b * SEQ;

    for (int i = tid; i < NTAG * NTAG; i += 64) str[i] = tr[i];
    __syncthreads();
    if (tid < NTAG) {
#pragma unroll 9
        for (int i = 0; i < NTAG; ++i)
            sE[i * 48 + tid] = __expf(str[i * NTAG + tid]);
    }

    // gold score partials (emission + transition terms)
    float part = 0.f;
    for (int s = tid; s < SEQ; s += 64) {
        int cur = tg[s];
        part += g_em[(size_t)(b * SEQ + s) * NTAG + cur];
        if (s + 1 < SEQ) part += str[cur * NTAG + tg[s + 1]];
    }
    rbuf[tid] = part;
    if (tid < NTAG) ab[0][tid] = st[tid] + g_em[(size_t)(b * SEQ) * NTAG + tid];
    __syncthreads();

    int cur = 0;
    for (int t = 1; t < SEQ; ++t) {
        float m = -1e30f;
        if (tid < NTAG) {
            const float* al = ab[cur];
            float m0 = -1e30f, m1 = -1e30f, m2 = -1e30f, m3 = -1e30f;
#pragma unroll 11
            for (int i = 0; i < 44; i += 4) {
                m0 = fmaxf(m0, al[i]);
                m1 = fmaxf(m1, al[i + 1]);
                m2 = fmaxf(m2, al[i + 2]);
                m3 = fmaxf(m3, al[i + 3]);
            }
            m = fmaxf(fmaxf(fmaxf(m0, m1), fmaxf(m2, m3)), al[44]);
            ea[tid] = __expf(al[tid] - m);
        }
        __syncthreads();
        if (tid < NTAG) {
            float s0 = 0.f, s1 = 0.f, s2 = 0.f, s3 = 0.f;
#pragma unroll 11
            for (int i = 0; i < 44; i += 4) {
                s0 += sE[(i    ) * 48 + tid] * ea[i];
                s1 += sE[(i + 1) * 48 + tid] * ea[i + 1];
                s2 += sE[(i + 2) * 48 + tid] * ea[i + 2];
                s3 += sE[(i + 3) * 48 + tid] * ea[i + 3];
            }
            float ssum = (s0 + s1) + (s2 + s3) + sE[44 * 48 + tid] * ea[44];
            ab[cur ^ 1][tid] = m + __logf(ssum) + g_em[(size_t)(b * SEQ + t) * NTAG + tid];
        }
        __syncthreads();
        cur ^= 1;
    }

    if (tid == 0) {
        float sc = 0.f;
        for (int i = 0; i < 64; ++i) sc += rbuf[i];          // fixed order: deterministic
        sc += st[tg[0]] + et[tg[SEQ - 1]];
        const float* al = ab[cur];
        float m = -1e30f;
        for (int j = 0; j < NTAG; ++j) m = fmaxf(m, al[j] + et[j]);
        float ssum = 0.f;
        for (int j = 0; j < NTAG; ++j) ssum += __expf(al[j] + et[j] - m);
        float logZ = m + __logf(ssum);
        g_loss[b] = logZ - sc;                               // per-sample NLL
    }
}

__global__ void final_reduce(float* __restrict__ out)
{
    if (threadIdx.x == 0) {
        float s = 0.f;
        for (int i = 0; i < BSZ; ++i) s += g_loss[i];
        out[0] = s / (float)BSZ;
    }
}

// =====================================================================
extern "C" void kernel_launch(void* const* d_in, const int* in_sizes, int n_in,
                              void* d_out, int out_size)
{
    (void)in_sizes; (void)n_in; (void)out_size;
    const int*   x   = (const int*)d_in[0];
    const int*   tgs = (const int*)d_in[1];
    const float* emb = (const float*)d_in[2];
    const float* wif = (const float*)d_in[3];
    const float* whf = (const float*)d_in[4];
    const float* bf  = (const float*)d_in[5];
    const float* wib = (const float*)d_in[6];
    const float* whb = (const float*)d_in[7];
    const float* bb  = (const float*)d_in[8];
    const float* lw  = (const float*)d_in[9];
    const float* lb  = (const float*)d_in[10];
    const float* st  = (const float*)d_in[11];
    const float* et  = (const float*)d_in[12];
    const float* tr  = (const float*)d_in[13];
    float* out = (float*)d_out;

    const int rec_smem = (48 * RS + 256 * 36) * 4;   // 146688 B
    cudaFuncSetAttribute(lstm_rec, cudaFuncAttributeMaxDynamicSharedMemorySize, rec_smem);

    dim3 gemm_grid(32, 64);
    gemm_in<<<gemm_grid, 256>>>(x, emb, wif, wib, bf, bb);
    lstm_rec<<<128, 256, rec_smem>>>(whf, whb);
    emis_k<<<256, 256>>>(lw, lb);
    crf_k<<<BSZ, 64>>>(tgs, st, et, tr);
    final_reduce<<<1, 32>>>(out);
}

// round 6
// speedup vs baseline: 1.5084x; 1.0798x over previous
#include <cuda_runtime.h>
#include <cstdint>
#include <cstddef>

#define BSZ 32
#define SEQ 256
#define EMBD 256
#define HIDD 512
#define NTAG 45
#define NTOK (BSZ*SEQ)     // 8192
#define G4H  2048          // 4*HID
#define GN   4096          // both directions
#define RS   572           // smem row stride (floats)

typedef unsigned long long u64v2;   // packed f32x2

__device__ __forceinline__ void fma2_(u64v2& d, u64v2 a, u64v2 b) {
    asm("fma.rn.f32x2 %0, %1, %2, %0;" : "+l"(d) : "l"(a), "l"(b));
}
__device__ __forceinline__ float unpack_sum_(u64v2 v) {
    float lo, hi;
    asm("mov.b64 {%0, %1}, %2;" : "=f"(lo), "=f"(hi) : "l"(v));
    return lo + hi;
}
__device__ __forceinline__ u64v2 pack2_(float lo, float hi) {
    u64v2 r;
    asm("mov.b64 %0, {%1, %2};" : "=l"(r) : "f"(lo), "f"(hi));
    return r;
}

// ---------------- scratch ----------------
__device__ __align__(16) float g_G[(size_t)NTOK * GN];           // input proj + bias
__device__ __align__(16) float g_hseq[2 * SEQ * BSZ * HIDD];     // [dir][t][b][h]
__device__ __align__(16) float g_em[(size_t)NTOK * NTAG];        // emissions
__device__ float g_loss[BSZ];
__device__ unsigned g_cnt4[4 * 32];                              // padded barrier slots
__device__ unsigned g_gen4[4 * 32];                              // monotonic generations

// =====================================================================
// Kernel 1: G[token][n] = dot(emb[x[token]], W[n]) + bias[n]
// f32x2 inner product: b-tile pairs come free from LDS.128 reg pairs.
// =====================================================================
__global__ __launch_bounds__(256) void gemm_in(
    const int* __restrict__ x, const float* __restrict__ emb,
    const float* __restrict__ wf, const float* __restrict__ wb,
    const float* __restrict__ bf, const float* __restrict__ bb)
{
    __shared__ float sA[16 * 132];
    __shared__ float sW[16 * 132];
    const int tid = threadIdx.x;
    const int bx = blockIdx.x;
    const int by = blockIdx.y;
    const int tx = tid & 15, ty = tid >> 4;

    u64v2 acc2[8][4];
#pragma unroll
    for (int i = 0; i < 8; ++i)
#pragma unroll
        for (int j = 0; j < 4; ++j) acc2[i][j] = 0ull;

    const int f4a = tid * 2, f4b = tid * 2 + 1;
    const int ra = f4a >> 2, qa = (f4a & 3) * 4;
    const int rb = f4b >> 2, qb = (f4b & 3) * 4;
    const float* arow_a = emb + (size_t)x[by * 128 + ra] * EMBD;
    const float* arow_b = emb + (size_t)x[by * 128 + rb] * EMBD;
    const int na = bx * 128 + ra, nb = bx * 128 + rb;
    const float* wrow_a = (na < G4H) ? (wf + (size_t)na * EMBD) : (wb + (size_t)(na - G4H) * EMBD);
    const float* wrow_b = (nb < G4H) ? (wf + (size_t)nb * EMBD) : (wb + (size_t)(nb - G4H) * EMBD);

    for (int kb = 0; kb < EMBD; kb += 16) {
        __syncthreads();
        float4 va = *(const float4*)(arow_a + kb + qa);
        float4 vb = *(const float4*)(arow_b + kb + qb);
        float4 wa = *(const float4*)(wrow_a + kb + qa);
        float4 wv = *(const float4*)(wrow_b + kb + qb);
        sA[(qa + 0) * 132 + ra] = va.x; sA[(qa + 1) * 132 + ra] = va.y;
        sA[(qa + 2) * 132 + ra] = va.z; sA[(qa + 3) * 132 + ra] = va.w;
        sA[(qb + 0) * 132 + rb] = vb.x; sA[(qb + 1) * 132 + rb] = vb.y;
        sA[(qb + 2) * 132 + rb] = vb.z; sA[(qb + 3) * 132 + rb] = vb.w;
        sW[(qa + 0) * 132 + ra] = wa.x; sW[(qa + 1) * 132 + ra] = wa.y;
        sW[(qa + 2) * 132 + ra] = wa.z; sW[(qa + 3) * 132 + ra] = wa.w;
        sW[(qb + 0) * 132 + rb] = wv.x; sW[(qb + 1) * 132 + rb] = wv.y;
        sW[(qb + 2) * 132 + rb] = wv.z; sW[(qb + 3) * 132 + rb] = wv.w;
        __syncthreads();
#pragma unroll
        for (int kk = 0; kk < 16; ++kk) {
            float4 a0 = *(const float4*)&sA[kk * 132 + ty * 8];
            float4 a1 = *(const float4*)&sA[kk * 132 + ty * 8 + 4];
            ulonglong2 b0 = *(const ulonglong2*)&sW[kk * 132 + tx * 8];     // j pairs (0,1),(2,3)
            ulonglong2 b1 = *(const ulonglong2*)&sW[kk * 132 + tx * 8 + 4]; // j pairs (4,5),(6,7)
            float av[8] = {a0.x, a0.y, a0.z, a0.w, a1.x, a1.y, a1.z, a1.w};
#pragma unroll
            for (int i = 0; i < 8; ++i) {
                u64v2 aa = pack2_(av[i], av[i]);
                fma2_(acc2[i][0], aa, b0.x);
                fma2_(acc2[i][1], aa, b0.y);
                fma2_(acc2[i][2], aa, b1.x);
                fma2_(acc2[i][3], aa, b1.y);
            }
        }
    }
    const int m0 = by * 128 + ty * 8;
    const int n0 = bx * 128 + tx * 8;
#pragma unroll
    for (int i = 0; i < 8; ++i) {
        float* dst = g_G + (size_t)(m0 + i) * GN + n0;
#pragma unroll
        for (int p = 0; p < 4; ++p) {
            float lo, hi;
            asm("mov.b64 {%0, %1}, %2;" : "=f"(lo), "=f"(hi) : "l"(acc2[i][p]));
            int n_lo = n0 + 2 * p, n_hi = n_lo + 1;
            float bias_lo = (n_lo < G4H) ? bf[n_lo] : bb[n_lo - G4H];
            float bias_hi = (n_hi < G4H) ? bf[n_hi] : bb[n_hi - G4H];
            dst[2 * p]     = lo + bias_lo;
            dst[2 * p + 1] = hi + bias_hi;
        }
    }
}

// =====================================================================
// Kernel 2: persistent bidirectional LSTM recurrence.
// PROVEN R3 barrier: atomicAdd arrivals + volatile generation poll.
// f32x2 packed FMA in the recurrent dot (k-pairs free from LDS.128).
// =====================================================================
__device__ __forceinline__ float sigmoidf_(float v) { return 1.f / (1.f + __expf(-v)); }

__global__ __launch_bounds__(256) void lstm_rec(
    const float* __restrict__ whf, const float* __restrict__ whb)
{
    extern __shared__ float smem[];
    float* sw  = smem;                 // 32 rows x RS
    float* sh  = smem + 32 * RS;       // 16 rows x RS
    float* red = smem + 48 * RS;       // [16 kseg][16 unit] x 36

    const int tid = threadIdx.x;
    const int dir = blockIdx.x >> 6;
    const int blk = blockIdx.x & 63;
    const int jbase = blk * 8;
    const float* whh = dir ? whb : whf;

    for (int idx = tid; idx < 32 * 128; idx += 256) {
        int row = idx >> 7;
        int q4 = idx & 127;
        int g = row >> 3, j = row & 7;
        float4 v = *(const float4*)(whh + (size_t)(g * 512 + jbase + j) * HIDD + q4 * 4);
        *(float4*)&sw[row * RS + q4 * 4 + 4 * (q4 >> 3)] = v;
    }

    const int kseg = tid >> 4;
    const int unit = tid & 15;
    const int jj = unit & 7;
    const int bo = unit >> 3;
    const int kb = kseg * 36;

    const int fj = tid & 7;
    const int fb = tid >> 3;
    const int jglob = jbase + fj;
    const int fgrp = fb >> 4;
    const int fbl = fb & 15;
    const int funit = fj + 8 * (fbl >> 3);
    const int fbb = fbl & 7;

    // base generations (replay-safe: captured before this block's first arrive)
    unsigned gb0 = 0, gb1 = 0;
    if (tid == 0) {
        gb0 = *(volatile unsigned*)&g_gen4[(dir * 2 + 0) * 32];
        gb1 = *(volatile unsigned*)&g_gen4[(dir * 2 + 1) * 32];
    }

    float c_state = 0.f;
    __syncthreads();

    for (int t = 0; t < SEQ; ++t) {
        const int t_eff = dir ? (SEQ - 1 - t) : t;
        const float* Grow = g_G + (size_t)(fb * SEQ + t_eff) * GN + dir * G4H;
        float pg0 = __ldg(Grow + jglob);
        float pg1 = __ldg(Grow + 512 + jglob);
        float pg2 = __ldg(Grow + 1024 + jglob);
        float pg3 = __ldg(Grow + 1536 + jglob);

#pragma unroll
        for (int grp = 0; grp < 2; ++grp) {
            const int slot = (dir * 2 + grp) * 32;
            float d0 = 0.f, d1 = 0.f, d2 = 0.f, d3 = 0.f;
            if (t > 0) {
                if (tid == 0) {
                    unsigned base = grp ? gb1 : gb0;
                    while ((unsigned)(*(volatile unsigned*)&g_gen4[slot] - base) < (unsigned)t) { }
                    __threadfence();
                }
                __syncthreads();
                // stage h_prev (group's 16 batches), k-swizzled
                const int prev_te = dir ? (t_eff + 1) : (t_eff - 1);
                const float* hsrc = g_hseq + (size_t)((dir * SEQ + prev_te) * BSZ + grp * 16) * HIDD;
                for (int idx = tid; idx < 16 * 128; idx += 256) {
                    int b = idx >> 7;
                    int q4 = idx & 127;
                    float4 v = __ldcg((const float4*)(hsrc + b * HIDD + q4 * 4));
                    *(float4*)&sh[b * RS + q4 * 4 + 4 * (q4 >> 3)] = v;
                }
                __syncthreads();
                u64v2 acc2[4][8];
#pragma unroll
                for (int g = 0; g < 4; ++g)
#pragma unroll
                    for (int bb = 0; bb < 8; ++bb) acc2[g][bb] = 0ull;
                const float* w0p = &sw[jj * RS + kb];
                const float* w1p = w0p + 8 * RS;
                const float* w2p = w0p + 16 * RS;
                const float* w3p = w0p + 24 * RS;
                const float* hp  = &sh[(bo * 8) * RS + kb];
#pragma unroll
                for (int kk = 0; kk < 32; kk += 4) {
                    ulonglong2 w0 = *(const ulonglong2*)(w0p + kk);  // k-pairs (k0k1, k2k3)
                    ulonglong2 w1 = *(const ulonglong2*)(w1p + kk);
                    ulonglong2 w2 = *(const ulonglong2*)(w2p + kk);
                    ulonglong2 w3 = *(const ulonglong2*)(w3p + kk);
#pragma unroll
                    for (int bb = 0; bb < 8; ++bb) {
                        ulonglong2 h = *(const ulonglong2*)(hp + bb * RS + kk);
                        fma2_(acc2[0][bb], w0.x, h.x); fma2_(acc2[0][bb], w0.y, h.y);
                        fma2_(acc2[1][bb], w1.x, h.x); fma2_(acc2[1][bb], w1.y, h.y);
                        fma2_(acc2[2][bb], w2.x, h.x); fma2_(acc2[2][bb], w2.y, h.y);
                        fma2_(acc2[3][bb], w3.x, h.x); fma2_(acc2[3][bb], w3.y, h.y);
                    }
                }
                float* rp = &red[(kseg * 16 + unit) * 36];
#pragma unroll
                for (int g = 0; g < 4; ++g) {
                    float s0 = unpack_sum_(acc2[g][0]);
                    float s1 = unpack_sum_(acc2[g][1]);
                    float s2 = unpack_sum_(acc2[g][2]);
                    float s3 = unpack_sum_(acc2[g][3]);
                    float s4 = unpack_sum_(acc2[g][4]);
                    float s5 = unpack_sum_(acc2[g][5]);
                    float s6 = unpack_sum_(acc2[g][6]);
                    float s7 = unpack_sum_(acc2[g][7]);
                    *(float4*)&rp[g * 8]     = make_float4(s0, s1, s2, s3);
                    *(float4*)&rp[g * 8 + 4] = make_float4(s4, s5, s6, s7);
                }
                __syncthreads();
                if (fgrp == grp) {
#pragma unroll
                    for (int s = 0; s < 16; ++s) {
                        const float* rr = &red[(s * 16 + funit) * 36];
                        d0 += rr[fbb];
                        d1 += rr[8 + fbb];
                        d2 += rr[16 + fbb];
                        d3 += rr[24 + fbb];
                    }
                }
            }
            if (fgrp == grp) {
                float gi = pg0 + d0;
                float gf = pg1 + d1;
                float gg = pg2 + d2;
                float go = pg3 + d3;
                float iv = sigmoidf_(gi);
                float fv = sigmoidf_(gf);
                float ov = sigmoidf_(go);
                float gv = tanhf(gg);
                c_state = fv * c_state + iv * gv;
                float hv = ov * tanhf(c_state);
                __stcg(&g_hseq[(size_t)((dir * SEQ + t_eff) * BSZ + fb) * HIDD + jglob], hv);
            }
            __threadfence();
            __syncthreads();
            if (tid == 0) {
                if (atomicAdd(&g_cnt4[slot], 1u) == 63u) {
                    g_cnt4[slot] = 0u;
                    __threadfence();
                    *(volatile unsigned*)&g_gen4[slot] =
                        *(volatile unsigned*)&g_gen4[slot] + 1u;
                }
            }
        }
    }
}

// =====================================================================
// Kernel 3: emissions
// =====================================================================
__device__ __forceinline__ float dot4_(float4 a, float4 b) {
    return a.x * b.x + a.y * b.y + a.z * b.z + a.w * b.w;
}

__global__ __launch_bounds__(256) void emis_k(
    const float* __restrict__ lw, const float* __restrict__ lb)
{
    __shared__ float shh[32 * 132];
    __shared__ float shw[48 * 132];
    const int tid = threadIdx.x;
    const int blk = blockIdx.x;
    const int b = blk >> 3;
    const int s0 = (blk & 7) * 32;
    const int tt = tid & 15;
    const int tg = tid >> 4;
    float acc[2][3] = {{0.f, 0.f, 0.f}, {0.f, 0.f, 0.f}};

    for (int kc = 0; kc < 1024; kc += 128) {
        __syncthreads();
        const int dk = kc >> 9;
        const int ko = kc & 511;
        for (int idx = tid; idx < 32 * 32; idx += 256) {
            int ti = idx >> 5;
            int q = (idx & 31) * 4;
            *(float4*)&shh[ti * 132 + q] =
                *(const float4*)&g_hseq[(size_t)((dk * SEQ + (s0 + ti)) * BSZ + b) * HIDD + ko + q];
        }
        for (int idx = tid; idx < 48 * 32; idx += 256) {
            int tag = idx >> 5;
            int q = (idx & 31) * 4;
            float4 v = make_float4(0.f, 0.f, 0.f, 0.f);
            if (tag < NTAG) v = *(const float4*)&lw[(size_t)tag * 1024 + kc + q];
            *(float4*)&shw[tag * 132 + q] = v;
        }
        __syncthreads();
#pragma unroll 8
        for (int kk = 0; kk < 128; kk += 4) {
            float4 h0 = *(const float4*)&shh[tt * 132 + kk];
            float4 h1 = *(const float4*)&shh[(tt + 16) * 132 + kk];
            float4 w0 = *(const float4*)&shw[tg * 132 + kk];
            float4 w1 = *(const float4*)&shw[(tg + 16) * 132 + kk];
            float4 w2 = *(const float4*)&shw[(tg + 32) * 132 + kk];
            acc[0][0] += dot4_(h0, w0); acc[0][1] += dot4_(h0, w1); acc[0][2] += dot4_(h0, w2);
            acc[1][0] += dot4_(h1, w0); acc[1][1] += dot4_(h1, w1); acc[1][2] += dot4_(h1, w2);
        }
    }
#pragma unroll
    for (int ti = 0; ti < 2; ++ti) {
        int token = b * SEQ + s0 + tt + ti * 16;
#pragma unroll
        for (int c = 0; c < 3; ++c) {
            int tag = tg + c * 16;
            if (tag < NTAG)
                g_em[(size_t)token * NTAG + tag] = acc[ti][c] + lb[tag];
        }
    }
}

// =====================================================================
// Kernel 4: CRF — exp-domain forward with lazy renorm (every 8 steps).
// =====================================================================
__global__ __launch_bounds__(64) void crf_k(
    const int* __restrict__ tags, const float* __restrict__ st,
    const float* __restrict__ et, const float* __restrict__ tr)
{
    __shared__ float str[NTAG * NTAG];
    __shared__ float sE[NTAG * 48];
    __shared__ float ab[2][48];
    __shared__ float rbuf[64];
    __shared__ float smax;
    const int tid = threadIdx.x;
    const int b = blockIdx.x;
    const int* tg = tags + b * SEQ;

    for (int i = tid; i < NTAG * NTAG; i += 64) str[i] = tr[i];
    __syncthreads();
    if (tid < NTAG) {
#pragma unroll 9
        for (int i = 0; i < NTAG; ++i)
            sE[i * 48 + tid] = __expf(str[i * NTAG + tid]);
    }

    // gold score partials
    float part = 0.f;
    for (int s = tid; s < SEQ; s += 64) {
        int cur = tg[s];
        part += g_em[(size_t)(b * SEQ + s) * NTAG + cur];
        if (s + 1 < SEQ) part += str[cur * NTAG + tg[s + 1]];
    }
    rbuf[tid] = part;
    if (tid < NTAG) ab[0][tid] = st[tid] + g_em[(size_t)(b * SEQ) * NTAG + tid];
    __syncthreads();

    // initial renorm -> exp domain
    if (tid < 32) {
        float v = (tid < NTAG) ? ab[0][tid] : -1e30f;
        float v2 = (tid + 32 < NTAG) ? ab[0][tid + 32] : -1e30f;
        float m = fmaxf(v, v2);
#pragma unroll
        for (int off = 16; off; off >>= 1)
            m = fmaxf(m, __shfl_xor_sync(0xffffffffu, m, off));
        if (tid == 0) smax = m;
    }
    __syncthreads();
    float logacc = smax;
    if (tid < NTAG) ab[0][tid] = __expf(ab[0][tid] - smax);
    __syncthreads();

    int cur = 0;
    float emc = (tid < NTAG) ? __ldg(&g_em[(size_t)(b * SEQ + 1) * NTAG + tid]) : 0.f;
    for (int t = 1; t < SEQ; ++t) {
        float emn = 0.f;
        if (t + 1 < SEQ && tid < NTAG)
            emn = __ldg(&g_em[(size_t)(b * SEQ + t + 1) * NTAG + tid]);
        if (tid < NTAG) {
            const float* a = ab[cur];
            float s0 = 0.f, s1 = 0.f, s2 = 0.f, s3 = 0.f;
#pragma unroll 11
            for (int i = 0; i < 44; i += 4) {
                s0 += sE[(i    ) * 48 + tid] * a[i];
                s1 += sE[(i + 1) * 48 + tid] * a[i + 1];
                s2 += sE[(i + 2) * 48 + tid] * a[i + 2];
                s3 += sE[(i + 3) * 48 + tid] * a[i + 3];
            }
            float ssum = (s0 + s1) + (s2 + s3) + sE[44 * 48 + tid] * a[44];
            ab[cur ^ 1][tid] = ssum * __expf(emc);
        }
        cur ^= 1;
        if ((t & 7) == 0) {
            __syncthreads();
            if (tid < 32) {
                float v = (tid < NTAG) ? ab[cur][tid] : 0.f;
                float v2 = (tid + 32 < NTAG) ? ab[cur][tid + 32] : 0.f;
                float m = fmaxf(v, v2);
#pragma unroll
                for (int off = 16; off; off >>= 1)
                    m = fmaxf(m, __shfl_xor_sync(0xffffffffu, m, off));
                if (tid == 0) smax = m;
            }
            __syncthreads();
            float mm = smax;
            if (tid < NTAG) ab[cur][tid] *= (1.f / mm);
            logacc += __logf(mm);
            __syncthreads();
        } else {
            __syncthreads();
        }
        emc = emn;
    }

    if (tid == 0) {
        float sc = 0.f;
        for (int i = 0; i < 64; ++i) sc += rbuf[i];
        sc += st[tg[0]] + et[tg[SEQ - 1]];
        const float* a = ab[cur];
        float ssum = 0.f;
        for (int j = 0; j < NTAG; ++j) ssum += a[j] * __expf(et[j]);
        float logZ = logacc + __logf(ssum);
        g_loss[b] = logZ - sc;
    }
}

__global__ void final_reduce(float* __restrict__ out)
{
    if (threadIdx.x == 0) {
        float s = 0.f;
        for (int i = 0; i < BSZ; ++i) s += g_loss[i];
        out[0] = s / (float)BSZ;
    }
}

// =====================================================================
extern "C" void kernel_launch(void* const* d_in, const int* in_sizes, int n_in,
                              void* d_out, int out_size)
{
    (void)in_sizes; (void)n_in; (void)out_size;
    const int*   x   = (const int*)d_in[0];
    const int*   tgs = (const int*)d_in[1];
    const float* emb = (const float*)d_in[2];
    const float* wif = (const float*)d_in[3];
    const float* whf = (const float*)d_in[4];
    const float* bf  = (const float*)d_in[5];
    const float* wib = (const float*)d_in[6];
    const float* whb = (const float*)d_in[7];
    const float* bb  = (const float*)d_in[8];
    const float* lw  = (const float*)d_in[9];
    const float* lb  = (const float*)d_in[10];
    const float* st  = (const float*)d_in[11];
    const float* et  = (const float*)d_in[12];
    const float* tr  = (const float*)d_in[13];
    float* out = (float*)d_out;

    const int rec_smem = (48 * RS + 256 * 36) * 4;   // 146688 B
    cudaFuncSetAttribute(lstm_rec, cudaFuncAttributeMaxDynamicSharedMemorySize, rec_smem);

    dim3 gemm_grid(32, 64);
    gemm_in<<<gemm_grid, 256>>>(x, emb, wif, wib, bf, bb);
    lstm_rec<<<128, 256, rec_smem>>>(whf, whb);
    emis_k<<<256, 256>>>(lw, lb);
    crf_k<<<BSZ, 64>>>(tgs, st, et, tr);
    final_reduce<<<1, 32>>>(out);
}